// round 7
// baseline (speedup 1.0000x reference)
#include <cuda_runtime.h>
#include <math.h>

#define Nn 100000
#define Ee 400000
#define Gg 5000
#define Hh 128
#define ND 52
#define ED 16
#define BKK 32

// ---------------- scratch (static device globals; no runtime allocation) ----------------
__device__ float g_h0[Nn * ND];        // encoded node features (52)
__device__ float g_hA[Nn * Hh];
__device__ float g_hB[Nn * Hh];
__device__ float g_xl[Nn * Hh];
__device__ float g_xr[Nn * Hh];
__device__ float g_e[(Ee + Nn) * ED];  // edge features; rows [Ee, Ee+Nn) = self-loop attrs
__device__ int   g_deg[Nn];
__device__ int   g_off[Nn + 1];
__device__ int   g_cur[Nn];
__device__ int   g_srcs[Ee];
__device__ int   g_eids[Ee];
__device__ int   g_bsums[128];

#define BUF_H0 0
#define BUF_HA 1
#define BUF_HB 2
__device__ __forceinline__ float* bufsel(int id) {
    switch (id) {
        case BUF_H0: return g_h0;
        case BUF_HA: return g_hA;
        default:     return g_hB;
    }
}

// ---------------- zero-init + node encoder (merged) ----------------
__global__ void k_init_nodes(const float* __restrict__ x,
                             const float* __restrict__ atom_emb,
                             const float* __restrict__ bool_emb,
                             const float* __restrict__ Wn,
                             const float* __restrict__ bn,
                             float* __restrict__ dout) {
    int i = blockIdx.x * blockDim.x + threadIdx.x;
    if (i < Nn * ED) g_e[(size_t)Ee * ED + i] = 0.0f;   // loop-attr accumulators
    if (i < Gg * Hh) dout[i] = 0.0f;                     // pool output (values >= 0)
    if (i < Nn) g_deg[i] = 0;

    int n = i;
    if (n >= Nn) return;
    const float* xr = x + (size_t)n * 14;
    float* out = g_h0 + (size_t)n * ND;
    int ai = (int)xr[0];
#pragma unroll
    for (int k = 0; k < 16; k++) out[k] = atom_emb[ai * 16 + k];
    float xc[10];
#pragma unroll
    for (int i2 = 0; i2 < 10; i2++) xc[i2] = xr[1 + i2];
#pragma unroll
    for (int j = 0; j < 30; j++) {
        float s = bn[j];
#pragma unroll
        for (int i2 = 0; i2 < 10; i2++) s += xc[i2] * Wn[i2 * 30 + j];
        out[16 + j] = s;
    }
    int b0 = (int)xr[11], b1 = (int)xr[12], b2 = (int)xr[13];
    out[46] = bool_emb[b0 * 2];     out[47] = bool_emb[b0 * 2 + 1];
    out[48] = bool_emb[b1 * 2];     out[49] = bool_emb[b1 * 2 + 1];
    out[50] = bool_emb[b2 * 2];     out[51] = bool_emb[b2 * 2 + 1];
}

// ---------------- edge encoder + loop-attr accumulation + in-degree count --------------
__global__ void k_enc_edges(const float* __restrict__ ea,
                            const int* __restrict__ ei,
                            const float* __restrict__ bond_emb,
                            const float* __restrict__ bool_emb,
                            const float* __restrict__ We,
                            const float* __restrict__ be) {
    int e = blockIdx.x * blockDim.x + threadIdx.x;
    if (e >= Ee) return;
    const float* a = ea + (size_t)e * 6;
    float ev[ED];
    int bi = (int)a[0];
#pragma unroll
    for (int k = 0; k < 8; k++) ev[k] = bond_emb[bi * 8 + k];
    ev[8] = a[1] * We[0] + be[0];
    ev[9] = a[1] * We[1] + be[1];
    int b0 = (int)a[2], b1 = (int)a[3], b2 = (int)a[4];
    ev[10] = bool_emb[b0 * 2]; ev[11] = bool_emb[b0 * 2 + 1];
    ev[12] = bool_emb[b1 * 2]; ev[13] = bool_emb[b1 * 2 + 1];
    ev[14] = bool_emb[b2 * 2]; ev[15] = bool_emb[b2 * 2 + 1];
    float* out = g_e + (size_t)e * ED;
#pragma unroll
    for (int k = 0; k < ED; k++) out[k] = ev[k];
    int dst = ei[Ee + e];
    float* ls = g_e + ((size_t)Ee + dst) * ED;
#pragma unroll
    for (int k = 0; k < ED; k++) atomicAdd(&ls[k], ev[k]);
    atomicAdd(&g_deg[dst], 1);
}

// ---------------- CSR scan (block-level) + loop-attr mean division (merged) ------------
__global__ void k_scan1() {
    __shared__ int s[1024];
    int i = blockIdx.x * 1024 + threadIdx.x;
    int v = (i < Nn) ? g_deg[i] : 0;
    if (i < Nn) {
        float inv = 1.0f / fmaxf((float)v, 1.0f);
        float* ls = g_e + ((size_t)Ee + i) * ED;
#pragma unroll
        for (int k = 0; k < ED; k++) ls[k] *= inv;
    }
    s[threadIdx.x] = v;
    __syncthreads();
    for (int o = 1; o < 1024; o <<= 1) {
        int t = (threadIdx.x >= o) ? s[threadIdx.x - o] : 0;
        __syncthreads();
        s[threadIdx.x] += t;
        __syncthreads();
    }
    if (i < Nn) g_off[i] = s[threadIdx.x] - v;  // exclusive within block
    if (threadIdx.x == 1023) g_bsums[blockIdx.x] = s[1023];
}

// merged scan2+scan3: each block computes its bsums prefix in parallel, then applies
__global__ void k_scan23() {
    __shared__ int pre;
    int b = blockIdx.x;
    if (threadIdx.x == 0) pre = 0;
    __syncthreads();
    int v = (threadIdx.x < b) ? g_bsums[threadIdx.x] : 0;   // b <= 97 < 1024
#pragma unroll
    for (int o = 16; o > 0; o >>= 1) v += __shfl_xor_sync(0xffffffff, v, o);
    if ((threadIdx.x & 31) == 0 && v) atomicAdd(&pre, v);
    __syncthreads();
    int i = b * 1024 + threadIdx.x;
    if (i < Nn) {
        int o = g_off[i] + pre;
        g_off[i] = o;
        g_cur[i] = o;
    }
    if (i == 0) g_off[Nn] = Ee;
}

__global__ void k_scatter(const int* __restrict__ ei) {
    int e = blockIdx.x * blockDim.x + threadIdx.x;
    if (e >= Ee) return;
    int dst = ei[Ee + e];
    int p = atomicAdd(&g_cur[dst], 1);
    g_srcs[p] = ei[e];
    g_eids[p] = e;
}

// ---------------- fused fp32 GEMM pair: [xl | xr] = A[MxK] @ [Wl | Wr] + [bl | br] -----
// 128 rows x 256 cols per block, 512 threads, 8x8 micro-tile, A-tile TRANSPOSED in smem.
// All inner-loop smem reads are LDS.128: av = broadcast float4 x2, wv = stride-16B float4 x2.
__global__ __launch_bounds__(512) void k_gemm2(int a_id, int K,
                        const float* __restrict__ Wl, const float* __restrict__ bl,
                        const float* __restrict__ Wr, const float* __restrict__ br) {
    __shared__ float As[BKK][132];   // transposed A tile; 132-stride keeps 16B alignment
    __shared__ float Ws[BKK][256];
    const float* A = bufsel(a_id);

    int tid = threadIdx.x;
    int tx = tid & 31, ty = tid >> 5;
    int row0 = blockIdx.x * 128;

    float acc[8][8];
#pragma unroll
    for (int i = 0; i < 8; i++)
#pragma unroll
        for (int j = 0; j < 8; j++) acc[i][j] = 0.0f;

    float4 blv = *(const float4*)&bl[tx * 4];
    float4 brv = *(const float4*)&br[tx * 4];

    for (int kb = 0; kb < K; kb += BKK) {
        // A tile: 128x32 floats = 1024 float4 loads, 2 per thread, scatter-transpose into As
#pragma unroll
        for (int f = tid; f < 1024; f += 512) {
            int r = f >> 3, c4 = (f & 7) << 2;
            int gr = row0 + r, gk = kb + c4;
            float4 v = make_float4(0.f, 0.f, 0.f, 0.f);
            if (gr < Nn) {
                const float* ap = A + (size_t)gr * K + gk;
                if (gk + 3 < K) v = *(const float4*)ap;
                else {
                    if (gk     < K) v.x = ap[0];
                    if (gk + 1 < K) v.y = ap[1];
                    if (gk + 2 < K) v.z = ap[2];
                }
            }
            As[c4 + 0][r] = v.x; As[c4 + 1][r] = v.y;
            As[c4 + 2][r] = v.z; As[c4 + 3][r] = v.w;
        }
        // W tile [32 x 256] = [Wl chunk | Wr chunk]: 2048 float4, 4 per thread
#pragma unroll
        for (int f = tid; f < 2048; f += 512) {
            int k = f >> 6, c4 = (f & 63) << 2;
            int gk = kb + k;
            float4 v = make_float4(0.f, 0.f, 0.f, 0.f);
            if (gk < K) {
                v = (c4 < 128) ? *(const float4*)(Wl + (size_t)gk * 128 + c4)
                               : *(const float4*)(Wr + (size_t)gk * 128 + (c4 - 128));
            }
            *(float4*)&Ws[k][c4] = v;
        }
        __syncthreads();

#pragma unroll 8
        for (int k = 0; k < BKK; k++) {
            float4 a0 = *(const float4*)&As[k][ty * 8];
            float4 a1 = *(const float4*)&As[k][ty * 8 + 4];
            float4 w0 = *(const float4*)&Ws[k][tx * 4];
            float4 w1 = *(const float4*)&Ws[k][128 + tx * 4];
            float av[8] = {a0.x, a0.y, a0.z, a0.w, a1.x, a1.y, a1.z, a1.w};
            float wv[8] = {w0.x, w0.y, w0.z, w0.w, w1.x, w1.y, w1.z, w1.w};
#pragma unroll
            for (int i = 0; i < 8; i++)
#pragma unroll
                for (int j = 0; j < 8; j++) acc[i][j] += av[i] * wv[j];
        }
        __syncthreads();
    }

#pragma unroll
    for (int i = 0; i < 8; i++) {
        int r = row0 + ty * 8 + i;
        if (r < Nn) {
            float4 ol = make_float4(acc[i][0] + blv.x, acc[i][1] + blv.y,
                                    acc[i][2] + blv.z, acc[i][3] + blv.w);
            float4 orr = make_float4(acc[i][4] + brv.x, acc[i][5] + brv.y,
                                     acc[i][6] + brv.z, acc[i][7] + brv.w);
            *(float4*)(g_xl + (size_t)r * Hh + tx * 4) = ol;
            *(float4*)(g_xr + (size_t)r * Hh + tx * 4) = orr;
        }
    }
}

// ---------------- GATv2 aggregation: warp/node, online softmax, pipelined gather --------
__global__ void k_gat(const float* __restrict__ Wedge, const float* __restrict__ att,
                      const float* __restrict__ bias, int hout_id,
                      int dopool, const int* __restrict__ batch, float* __restrict__ dout) {
    __shared__ float Ws[ED][Hh];
    __shared__ float atts[Hh];
    const float* xl = g_xl;
    const float* xr = g_xr;
    float* hout = bufsel(hout_id);
    int tid = threadIdx.x;
    for (int t = tid; t < ED * Hh; t += blockDim.x) Ws[t >> 7][t & 127] = Wedge[t];
    if (tid < Hh) atts[tid] = att[tid];
    __syncthreads();

    int warp = tid >> 5, lane = tid & 31;
    int n = blockIdx.x * (blockDim.x >> 5) + warp;
    if (n >= Nn) return;
    int c0 = lane * 4;

    const float4 xr4 = *(const float4*)(xr + (size_t)n * Hh + c0);
    const float4 at4 = *(const float4*)&atts[c0];

    float mrun = -1e30f, srun = 0.0f;
    float ac0 = 0.0f, ac1 = 0.0f, ac2 = 0.0f, ac3 = 0.0f;
    int beg = g_off[n], end = g_off[n + 1];

    // prime the pipeline (idx = beg; self-loop if no edges)
    int src = n, eid = Ee + n;
    if (beg < end) { src = g_srcs[beg]; eid = g_eids[beg]; }
    float4 xl4 = *(const float4*)(xl + (size_t)src * Hh + c0);
    const float4* evp = (const float4*)(g_e + (size_t)eid * ED);
    float4 e0 = evp[0], e1 = evp[1], e2 = evp[2], e3 = evp[3];

    for (int it = beg; it <= end; it++) {
        // prefetch next edge's data before computing on current
        int nit = it + 1;
        float4 nxl4, ne0, ne1, ne2, ne3;
        bool have_next = (nit <= end);
        if (have_next) {
            int nsrc = n, neid = Ee + n;
            if (nit < end) { nsrc = g_srcs[nit]; neid = g_eids[nit]; }
            nxl4 = *(const float4*)(xl + (size_t)nsrc * Hh + c0);
            const float4* nevp = (const float4*)(g_e + (size_t)neid * ED);
            ne0 = nevp[0]; ne1 = nevp[1]; ne2 = nevp[2]; ne3 = nevp[3];
        }

        // edge-linear for this lane's 4 channels (float4 LDS, conflict-free)
        float el0 = 0.f, el1 = 0.f, el2 = 0.f, el3 = 0.f;
        float ev[ED] = {e0.x, e0.y, e0.z, e0.w, e1.x, e1.y, e1.z, e1.w,
                        e2.x, e2.y, e2.z, e2.w, e3.x, e3.y, e3.z, e3.w};
#pragma unroll
        for (int j = 0; j < ED; j++) {
            const float4 wj = *(const float4*)&Ws[j][c0];
            float e = ev[j];
            el0 += e * wj.x; el1 += e * wj.y; el2 += e * wj.z; el3 += e * wj.w;
        }
        float m0 = xl4.x + xr4.x + el0;
        float m1 = xl4.y + xr4.y + el1;
        float m2 = xl4.z + xr4.z + el2;
        float m3 = xl4.w + xr4.w + el3;
        float l0 = m0 > 0.0f ? m0 : 0.2f * m0;
        float l1 = m1 > 0.0f ? m1 : 0.2f * m1;
        float l2 = m2 > 0.0f ? m2 : 0.2f * m2;
        float l3 = m3 > 0.0f ? m3 : 0.2f * m3;
        float p = l0 * at4.x + l1 * at4.y + l2 * at4.z + l3 * at4.w;
#pragma unroll
        for (int o = 16; o > 0; o >>= 1) p += __shfl_xor_sync(0xffffffff, p, o);

        float nm = fmaxf(mrun, p);
        float sc = expf(mrun - nm);
        float w  = expf(p - nm);
        srun = srun * sc + w;
        ac0 = ac0 * sc + w * xl4.x;
        ac1 = ac1 * sc + w * xl4.y;
        ac2 = ac2 * sc + w * xl4.z;
        ac3 = ac3 * sc + w * xl4.w;
        mrun = nm;

        if (have_next) { xl4 = nxl4; e0 = ne0; e1 = ne1; e2 = ne2; e3 = ne3; }
    }

    float inv = 1.0f / srun;
    float o0 = fmaxf(ac0 * inv + bias[c0],     0.0f);
    float o1 = fmaxf(ac1 * inv + bias[c0 + 1], 0.0f);
    float o2 = fmaxf(ac2 * inv + bias[c0 + 2], 0.0f);
    float o3 = fmaxf(ac3 * inv + bias[c0 + 3], 0.0f);
    *(float4*)(hout + (size_t)n * Hh + c0) = make_float4(o0, o1, o2, o3);

    if (dopool) {
        int b = batch[n];
        int* dp = (int*)(dout + (size_t)b * Hh + c0);
        atomicMax(dp,     __float_as_int(o0));
        atomicMax(dp + 1, __float_as_int(o1));
        atomicMax(dp + 2, __float_as_int(o2));
        atomicMax(dp + 3, __float_as_int(o3));
    }
}

// ---------------- host launcher (kernel launches only; graph-capture safe) ----------------
extern "C" void kernel_launch(void* const* d_in, const int* in_sizes, int n_in,
                              void* d_out, int out_size) {
    const float* x        = (const float*)d_in[0];
    const int*   ei       = (const int*)d_in[1];
    const float* ea       = (const float*)d_in[2];
    const int*   batch    = (const int*)d_in[3];
    const float* atom_emb = (const float*)d_in[4];
    const float* bond_emb = (const float*)d_in[5];
    const float* bool_emb = (const float*)d_in[6];
    const float* Wn  = (const float*)d_in[7];
    const float* bn  = (const float*)d_in[8];
    const float* We  = (const float*)d_in[9];
    const float* be  = (const float*)d_in[10];
    const float* Wl1 = (const float*)d_in[11];
    const float* bl1 = (const float*)d_in[12];
    const float* Wr1 = (const float*)d_in[13];
    const float* br1 = (const float*)d_in[14];
    const float* Wedge1 = (const float*)d_in[15];
    const float* att1   = (const float*)d_in[16];
    const float* bias1  = (const float*)d_in[17];
    const float* Wl2 = (const float*)d_in[18];
    const float* bl2 = (const float*)d_in[19];
    const float* Wr2 = (const float*)d_in[20];
    const float* br2 = (const float*)d_in[21];
    const float* Wedge2 = (const float*)d_in[22];
    const float* att2   = (const float*)d_in[23];
    const float* bias2  = (const float*)d_in[24];
    float* out = (float*)d_out;

    int gm = (Nn + 127) / 128;
    int ga = (Nn + 7) / 8;
    int nb = (Nn + 1023) / 1024;

    // prep; gemm layer-1 hoisted to 4th launch (only depends on g_h0) so ncu captures it
    k_init_nodes<<<(Nn * ED + 255) / 256, 256>>>(x, atom_emb, bool_emb, Wn, bn, out);
    k_enc_edges<<<(Ee + 255) / 256, 256>>>(ea, ei, bond_emb, bool_emb, We, be);
    k_scan1<<<nb, 1024>>>();
    k_gemm2<<<gm, 512>>>(BUF_H0, ND, Wl1, bl1, Wr1, br1);       // layer 1 GEMM (4th launch)
    k_scan23<<<nb, 1024>>>();
    k_scatter<<<(Ee + 255) / 256, 256>>>(ei);

    // layer 1 aggregate
    k_gat<<<ga, 256>>>(Wedge1, att1, bias1, BUF_HA, 0, batch, out);

    // layer 2 (shared weights W*2)
    k_gemm2<<<gm, 512>>>(BUF_HA, Hh, Wl2, bl2, Wr2, br2);
    k_gat<<<ga, 256>>>(Wedge2, att2, bias2, BUF_HB, 0, batch, out);

    // layer 3 (shared weights W*2) + fused global max pool
    k_gemm2<<<gm, 512>>>(BUF_HB, Hh, Wl2, bl2, Wr2, br2);
    k_gat<<<ga, 256>>>(Wedge2, att2, bias2, BUF_HA, 1, batch, out);
}

// round 8
// speedup vs baseline: 1.5345x; 1.5345x over previous
#include <cuda_runtime.h>
#include <math.h>

#define Nn 100000
#define Ee 400000
#define Gg 5000
#define Hh 128
#define ND 52
#define ED 16
#define BKK 32

// ---------------- scratch (static device globals; no runtime allocation) ----------------
__device__ float g_h0[Nn * ND];        // encoded node features (52)
__device__ float g_hA[Nn * Hh];
__device__ float g_hB[Nn * Hh];
__device__ float g_xl[Nn * Hh];
__device__ float g_xr[Nn * Hh];
__device__ float g_e[(Ee + Nn) * ED];  // edge features; rows [Ee, Ee+Nn) = self-loop attrs
__device__ float g_ec[Ee * ED];        // edge features permuted into CSR order
__device__ int   g_deg[Nn];
__device__ int   g_off[Nn + 1];
__device__ int   g_cur[Nn];
__device__ int   g_srcs[Ee];
__device__ int   g_bsums[128];

#define BUF_H0 0
#define BUF_HA 1
#define BUF_HB 2
__device__ __forceinline__ float* bufsel(int id) {
    switch (id) {
        case BUF_H0: return g_h0;
        case BUF_HA: return g_hA;
        default:     return g_hB;
    }
}

// ---------------- zero-init + node encoder (merged) ----------------
__global__ void k_init_nodes(const float* __restrict__ x,
                             const float* __restrict__ atom_emb,
                             const float* __restrict__ bool_emb,
                             const float* __restrict__ Wn,
                             const float* __restrict__ bn,
                             float* __restrict__ dout) {
    int i = blockIdx.x * blockDim.x + threadIdx.x;
    if (i < Nn * ED) g_e[(size_t)Ee * ED + i] = 0.0f;   // loop-attr accumulators
    if (i < Gg * Hh) dout[i] = 0.0f;                     // pool output (values >= 0)
    if (i < Nn) g_deg[i] = 0;

    int n = i;
    if (n >= Nn) return;
    const float* xr = x + (size_t)n * 14;
    float* out = g_h0 + (size_t)n * ND;
    int ai = (int)xr[0];
#pragma unroll
    for (int k = 0; k < 16; k++) out[k] = atom_emb[ai * 16 + k];
    float xc[10];
#pragma unroll
    for (int i2 = 0; i2 < 10; i2++) xc[i2] = xr[1 + i2];
#pragma unroll
    for (int j = 0; j < 30; j++) {
        float s = bn[j];
#pragma unroll
        for (int i2 = 0; i2 < 10; i2++) s += xc[i2] * Wn[i2 * 30 + j];
        out[16 + j] = s;
    }
    int b0 = (int)xr[11], b1 = (int)xr[12], b2 = (int)xr[13];
    out[46] = bool_emb[b0 * 2];     out[47] = bool_emb[b0 * 2 + 1];
    out[48] = bool_emb[b1 * 2];     out[49] = bool_emb[b1 * 2 + 1];
    out[50] = bool_emb[b2 * 2];     out[51] = bool_emb[b2 * 2 + 1];
}

// ---------------- edge encoder + loop-attr accumulation + in-degree count --------------
__global__ void k_enc_edges(const float* __restrict__ ea,
                            const int* __restrict__ ei,
                            const float* __restrict__ bond_emb,
                            const float* __restrict__ bool_emb,
                            const float* __restrict__ We,
                            const float* __restrict__ be) {
    int e = blockIdx.x * blockDim.x + threadIdx.x;
    if (e >= Ee) return;
    const float* a = ea + (size_t)e * 6;
    float ev[ED];
    int bi = (int)a[0];
#pragma unroll
    for (int k = 0; k < 8; k++) ev[k] = bond_emb[bi * 8 + k];
    ev[8] = a[1] * We[0] + be[0];
    ev[9] = a[1] * We[1] + be[1];
    int b0 = (int)a[2], b1 = (int)a[3], b2 = (int)a[4];
    ev[10] = bool_emb[b0 * 2]; ev[11] = bool_emb[b0 * 2 + 1];
    ev[12] = bool_emb[b1 * 2]; ev[13] = bool_emb[b1 * 2 + 1];
    ev[14] = bool_emb[b2 * 2]; ev[15] = bool_emb[b2 * 2 + 1];
    float* out = g_e + (size_t)e * ED;
#pragma unroll
    for (int k = 0; k < ED; k++) out[k] = ev[k];
    int dst = ei[Ee + e];
    float* ls = g_e + ((size_t)Ee + dst) * ED;
#pragma unroll
    for (int k = 0; k < ED; k++) atomicAdd(&ls[k], ev[k]);
    atomicAdd(&g_deg[dst], 1);
}

// ---------------- CSR scan (block-level) + loop-attr mean division (merged) ------------
__global__ void k_scan1() {
    __shared__ int s[1024];
    int i = blockIdx.x * 1024 + threadIdx.x;
    int v = (i < Nn) ? g_deg[i] : 0;
    if (i < Nn) {
        float inv = 1.0f / fmaxf((float)v, 1.0f);
        float* ls = g_e + ((size_t)Ee + i) * ED;
#pragma unroll
        for (int k = 0; k < ED; k++) ls[k] *= inv;
    }
    s[threadIdx.x] = v;
    __syncthreads();
    for (int o = 1; o < 1024; o <<= 1) {
        int t = (threadIdx.x >= o) ? s[threadIdx.x - o] : 0;
        __syncthreads();
        s[threadIdx.x] += t;
        __syncthreads();
    }
    if (i < Nn) g_off[i] = s[threadIdx.x] - v;  // exclusive within block
    if (threadIdx.x == 1023) g_bsums[blockIdx.x] = s[1023];
}

// merged scan2+scan3: each block computes its bsums prefix in parallel, then applies
__global__ void k_scan23() {
    __shared__ int pre;
    int b = blockIdx.x;
    if (threadIdx.x == 0) pre = 0;
    __syncthreads();
    int v = (threadIdx.x < b) ? g_bsums[threadIdx.x] : 0;   // b <= 97 < 1024
#pragma unroll
    for (int o = 16; o > 0; o >>= 1) v += __shfl_xor_sync(0xffffffff, v, o);
    if ((threadIdx.x & 31) == 0 && v) atomicAdd(&pre, v);
    __syncthreads();
    int i = b * 1024 + threadIdx.x;
    if (i < Nn) {
        int o = g_off[i] + pre;
        g_off[i] = o;
        g_cur[i] = o;
    }
    if (i == 0) g_off[Nn] = Ee;
}

// scatter + permute edge features into CSR order (paid once; read 3x streaming in gat)
__global__ void k_scatter(const int* __restrict__ ei) {
    int e = blockIdx.x * blockDim.x + threadIdx.x;
    if (e >= Ee) return;
    int dst = ei[Ee + e];
    int p = atomicAdd(&g_cur[dst], 1);
    g_srcs[p] = ei[e];
    const float4* src4 = (const float4*)(g_e + (size_t)e * ED);
    float4* dst4 = (float4*)(g_ec + (size_t)p * ED);
    dst4[0] = src4[0]; dst4[1] = src4[1]; dst4[2] = src4[2]; dst4[3] = src4[3];
}

// ---------------- fused fp32 GEMM pair: [xl | xr] = A[MxK] @ [Wl | Wr] + [bl | br] -----
// (unchanged from R7: measured 102.9us @ K=52)
__global__ __launch_bounds__(512) void k_gemm2(int a_id, int K,
                        const float* __restrict__ Wl, const float* __restrict__ bl,
                        const float* __restrict__ Wr, const float* __restrict__ br) {
    __shared__ float As[BKK][132];   // transposed A tile; 132-stride keeps 16B alignment
    __shared__ float Ws[BKK][256];
    const float* A = bufsel(a_id);

    int tid = threadIdx.x;
    int tx = tid & 31, ty = tid >> 5;
    int row0 = blockIdx.x * 128;

    float acc[8][8];
#pragma unroll
    for (int i = 0; i < 8; i++)
#pragma unroll
        for (int j = 0; j < 8; j++) acc[i][j] = 0.0f;

    float4 blv = *(const float4*)&bl[tx * 4];
    float4 brv = *(const float4*)&br[tx * 4];

    for (int kb = 0; kb < K; kb += BKK) {
#pragma unroll
        for (int f = tid; f < 1024; f += 512) {
            int r = f >> 3, c4 = (f & 7) << 2;
            int gr = row0 + r, gk = kb + c4;
            float4 v = make_float4(0.f, 0.f, 0.f, 0.f);
            if (gr < Nn) {
                const float* ap = A + (size_t)gr * K + gk;
                if (gk + 3 < K) v = *(const float4*)ap;
                else {
                    if (gk     < K) v.x = ap[0];
                    if (gk + 1 < K) v.y = ap[1];
                    if (gk + 2 < K) v.z = ap[2];
                }
            }
            As[c4 + 0][r] = v.x; As[c4 + 1][r] = v.y;
            As[c4 + 2][r] = v.z; As[c4 + 3][r] = v.w;
        }
#pragma unroll
        for (int f = tid; f < 2048; f += 512) {
            int k = f >> 6, c4 = (f & 63) << 2;
            int gk = kb + k;
            float4 v = make_float4(0.f, 0.f, 0.f, 0.f);
            if (gk < K) {
                v = (c4 < 128) ? *(const float4*)(Wl + (size_t)gk * 128 + c4)
                               : *(const float4*)(Wr + (size_t)gk * 128 + (c4 - 128));
            }
            *(float4*)&Ws[k][c4] = v;
        }
        __syncthreads();

#pragma unroll 8
        for (int k = 0; k < BKK; k++) {
            float4 a0 = *(const float4*)&As[k][ty * 8];
            float4 a1 = *(const float4*)&As[k][ty * 8 + 4];
            float4 w0 = *(const float4*)&Ws[k][tx * 4];
            float4 w1 = *(const float4*)&Ws[k][128 + tx * 4];
            float av[8] = {a0.x, a0.y, a0.z, a0.w, a1.x, a1.y, a1.z, a1.w};
            float wv[8] = {w0.x, w0.y, w0.z, w0.w, w1.x, w1.y, w1.z, w1.w};
#pragma unroll
            for (int i = 0; i < 8; i++)
#pragma unroll
                for (int j = 0; j < 8; j++) acc[i][j] += av[i] * wv[j];
        }
        __syncthreads();
    }

#pragma unroll
    for (int i = 0; i < 8; i++) {
        int r = row0 + ty * 8 + i;
        if (r < Nn) {
            float4 ol = make_float4(acc[i][0] + blv.x, acc[i][1] + blv.y,
                                    acc[i][2] + blv.z, acc[i][3] + blv.w);
            float4 orr = make_float4(acc[i][4] + brv.x, acc[i][5] + brv.y,
                                     acc[i][6] + brv.z, acc[i][7] + brv.w);
            *(float4*)(g_xl + (size_t)r * Hh + tx * 4) = ol;
            *(float4*)(g_xr + (size_t)r * Hh + tx * 4) = orr;
        }
    }
}

// ---------------- GATv2 aggregation: warp/node, online softmax, streaming CSR edges -----
// R6 structure (no payload prefetch) + index-only prefetch (+1 reg, shortens dep chain).
__global__ void k_gat(const float* __restrict__ Wedge, const float* __restrict__ att,
                      const float* __restrict__ bias, int hout_id,
                      int dopool, const int* __restrict__ batch, float* __restrict__ dout) {
    __shared__ float Ws[ED][Hh];
    __shared__ float atts[Hh];
    const float* xl = g_xl;
    const float* xr = g_xr;
    float* hout = bufsel(hout_id);
    int tid = threadIdx.x;
    for (int t = tid; t < ED * Hh; t += blockDim.x) Ws[t >> 7][t & 127] = Wedge[t];
    if (tid < Hh) atts[tid] = att[tid];
    __syncthreads();

    int warp = tid >> 5, lane = tid & 31;
    int n = blockIdx.x * (blockDim.x >> 5) + warp;
    if (n >= Nn) return;
    int c0 = lane * 4;

    const float4 xr4 = *(const float4*)(xr + (size_t)n * Hh + c0);
    const float4 at4 = *(const float4*)&atts[c0];

    float mrun = -1e30f, srun = 0.0f;
    float ac0 = 0.0f, ac1 = 0.0f, ac2 = 0.0f, ac3 = 0.0f;
    int beg = g_off[n], end = g_off[n + 1];

    int src_nxt = (beg < end) ? g_srcs[beg] : n;
    for (int it = beg; it <= end; it++) {
        int src = src_nxt;
        src_nxt = (it + 1 < end) ? g_srcs[it + 1] : n;

        const float4* evp = (it < end) ? (const float4*)(g_ec + (size_t)it * ED)
                                       : (const float4*)(g_e + ((size_t)Ee + n) * ED);
        float4 xl4 = *(const float4*)(xl + (size_t)src * Hh + c0);
        float4 e0 = evp[0], e1 = evp[1], e2 = evp[2], e3 = evp[3];

        float el0 = 0.f, el1 = 0.f, el2 = 0.f, el3 = 0.f;
        float ev[ED] = {e0.x, e0.y, e0.z, e0.w, e1.x, e1.y, e1.z, e1.w,
                        e2.x, e2.y, e2.z, e2.w, e3.x, e3.y, e3.z, e3.w};
#pragma unroll
        for (int j = 0; j < ED; j++) {
            const float4 wj = *(const float4*)&Ws[j][c0];
            float e = ev[j];
            el0 += e * wj.x; el1 += e * wj.y; el2 += e * wj.z; el3 += e * wj.w;
        }
        float m0 = xl4.x + xr4.x + el0;
        float m1 = xl4.y + xr4.y + el1;
        float m2 = xl4.z + xr4.z + el2;
        float m3 = xl4.w + xr4.w + el3;
        float l0 = m0 > 0.0f ? m0 : 0.2f * m0;
        float l1 = m1 > 0.0f ? m1 : 0.2f * m1;
        float l2 = m2 > 0.0f ? m2 : 0.2f * m2;
        float l3 = m3 > 0.0f ? m3 : 0.2f * m3;
        float p = l0 * at4.x + l1 * at4.y + l2 * at4.z + l3 * at4.w;
#pragma unroll
        for (int o = 16; o > 0; o >>= 1) p += __shfl_xor_sync(0xffffffff, p, o);

        float nm = fmaxf(mrun, p);
        float sc = expf(mrun - nm);
        float w  = expf(p - nm);
        srun = srun * sc + w;
        ac0 = ac0 * sc + w * xl4.x;
        ac1 = ac1 * sc + w * xl4.y;
        ac2 = ac2 * sc + w * xl4.z;
        ac3 = ac3 * sc + w * xl4.w;
        mrun = nm;
    }

    float inv = 1.0f / srun;
    float o0 = fmaxf(ac0 * inv + bias[c0],     0.0f);
    float o1 = fmaxf(ac1 * inv + bias[c0 + 1], 0.0f);
    float o2 = fmaxf(ac2 * inv + bias[c0 + 2], 0.0f);
    float o3 = fmaxf(ac3 * inv + bias[c0 + 3], 0.0f);
    *(float4*)(hout + (size_t)n * Hh + c0) = make_float4(o0, o1, o2, o3);

    if (dopool) {
        int b = batch[n];
        int* dp = (int*)(dout + (size_t)b * Hh + c0);
        atomicMax(dp,     __float_as_int(o0));
        atomicMax(dp + 1, __float_as_int(o1));
        atomicMax(dp + 2, __float_as_int(o2));
        atomicMax(dp + 3, __float_as_int(o3));
    }
}

// ---------------- host launcher (kernel launches only; graph-capture safe) ----------------
extern "C" void kernel_launch(void* const* d_in, const int* in_sizes, int n_in,
                              void* d_out, int out_size) {
    const float* x        = (const float*)d_in[0];
    const int*   ei       = (const int*)d_in[1];
    const float* ea       = (const float*)d_in[2];
    const int*   batch    = (const int*)d_in[3];
    const float* atom_emb = (const float*)d_in[4];
    const float* bond_emb = (const float*)d_in[5];
    const float* bool_emb = (const float*)d_in[6];
    const float* Wn  = (const float*)d_in[7];
    const float* bn  = (const float*)d_in[8];
    const float* We  = (const float*)d_in[9];
    const float* be  = (const float*)d_in[10];
    const float* Wl1 = (const float*)d_in[11];
    const float* bl1 = (const float*)d_in[12];
    const float* Wr1 = (const float*)d_in[13];
    const float* br1 = (const float*)d_in[14];
    const float* Wedge1 = (const float*)d_in[15];
    const float* att1   = (const float*)d_in[16];
    const float* bias1  = (const float*)d_in[17];
    const float* Wl2 = (const float*)d_in[18];
    const float* bl2 = (const float*)d_in[19];
    const float* Wr2 = (const float*)d_in[20];
    const float* br2 = (const float*)d_in[21];
    const float* Wedge2 = (const float*)d_in[22];
    const float* att2   = (const float*)d_in[23];
    const float* bias2  = (const float*)d_in[24];
    float* out = (float*)d_out;

    int gm = (Nn + 127) / 128;
    int ga = (Nn + 7) / 8;
    int nb = (Nn + 1023) / 1024;

    // prep; layer-1 GEMM kept as 4th launch (ncu window) for round-over-round comparison
    k_init_nodes<<<(Nn * ED + 255) / 256, 256>>>(x, atom_emb, bool_emb, Wn, bn, out);
    k_enc_edges<<<(Ee + 255) / 256, 256>>>(ea, ei, bond_emb, bool_emb, We, be);
    k_scan1<<<nb, 1024>>>();
    k_gemm2<<<gm, 512>>>(BUF_H0, ND, Wl1, bl1, Wr1, br1);       // layer 1 GEMM (4th launch)
    k_scan23<<<nb, 1024>>>();
    k_scatter<<<(Ee + 255) / 256, 256>>>(ei);

    // layer 1 aggregate
    k_gat<<<ga, 256>>>(Wedge1, att1, bias1, BUF_HA, 0, batch, out);

    // layer 2 (shared weights W*2)
    k_gemm2<<<gm, 512>>>(BUF_HA, Hh, Wl2, bl2, Wr2, br2);
    k_gat<<<ga, 256>>>(Wedge2, att2, bias2, BUF_HB, 0, batch, out);

    // layer 3 (shared weights W*2) + fused global max pool
    k_gemm2<<<gm, 512>>>(BUF_HB, Hh, Wl2, bl2, Wr2, br2);
    k_gat<<<ga, 256>>>(Wedge2, att2, bias2, BUF_HA, 1, batch, out);
}